// round 4
// baseline (speedup 1.0000x reference)
#include <cuda_runtime.h>
#include <cuda_bf16.h>

// DiagPooling: x [B=8, C=128, H=512, W=512] fp32 -> out [B, 1, 513] fp32
// out[b, 0, o] = (1 / (C * (512 - |o-256|))) * sum_{c, i} x[b, c, i, i + o - 256]
//
// Vectorized flat decomposition. A "slot" is one aligned float4 (4 columns)
// of one (b, row). Row p (p<256) starts at column 0 (aligned) and needs
// nvec1 = ceil((p+257)/4) slots; row p+256 starts at (p & ~3) (aligned
// down) and needs 128 - (p>>2) slots. Their sum is EXACTLY 193 for all p,
// so global slot id g in [0, 8*256*193 = 395264) decodes with constant
// arithmetic: b = g/49408, p = (g%49408)/193, s = (g%49408)%193.
// 395264 = 1544 blocks * 256 threads exactly -> every lane active, all
// blocks identical. Each thread: 128 x LDG.128 over channels into 4 column
// sums (two accumulator sets), then pre-scaled atomicAdd for the valid
// columns only (invalid edge columns share the sector anyway -> free).

#define B_DIM 8
#define C_DIM 128
#define H_DIM 512
#define W_DIM 512
#define N_OFF 513
#define OUT_ELEMS (B_DIM * N_OFF)

#define SLOTS_PER_PAIR 193
#define SLOTS_PER_BATCH (256 * SLOTS_PER_PAIR)      // 49408
#define TOTAL_SLOTS (B_DIM * SLOTS_PER_BATCH)       // 395264
#define NBLOCKS (TOTAL_SLOTS / 256)                 // 1544

__global__ void zero_out_kernel(float* __restrict__ out, int n) {
    int idx = blockIdx.x * blockDim.x + threadIdx.x;
    if (idx < n) out[idx] = 0.0f;
}

__global__ __launch_bounds__(256) void diag_pool_kernel(
    const float* __restrict__ x, float* __restrict__ out)
{
    const int g = blockIdx.x * 256 + threadIdx.x;   // global slot id

    const int b = g / SLOTS_PER_BATCH;
    const int r = g - b * SLOTS_PER_BATCH;
    const int p = r / SLOTS_PER_PAIR;               // pair 0..255
    const int s = r - p * SLOTS_PER_PAIR;           // slot within pair

    const int nvec1 = (p + 260) >> 2;               // ceil((p+257)/4)

    int i, jbase;
    if (s < nvec1) {                                // row p, columns [0, p+256]
        i = p;
        jbase = 4 * s;
    } else {                                        // row p+256, columns [p, 511]
        i = p + 256;
        jbase = (p & ~3) + 4 * (s - nvec1);
    }

    const size_t S = (size_t)H_DIM * W_DIM;         // channel stride (elements)
    const float* ptr = x + (size_t)b * C_DIM * S + (size_t)i * W_DIM + jbase;

    // Two independent accumulator sets per column to relax the FADD chain.
    float ax0 = 0.f, ay0 = 0.f, az0 = 0.f, aw0 = 0.f;
    float ax1 = 0.f, ay1 = 0.f, az1 = 0.f, aw1 = 0.f;

    #pragma unroll 8
    for (int c = 0; c < C_DIM; c += 2) {
        const float4 v0 = __ldg((const float4*)(ptr + (size_t)(c + 0) * S));
        const float4 v1 = __ldg((const float4*)(ptr + (size_t)(c + 1) * S));
        ax0 += v0.x; ay0 += v0.y; az0 += v0.z; aw0 += v0.w;
        ax1 += v1.x; ay1 += v1.y; az1 += v1.z; aw1 += v1.w;
    }

    float sum[4];
    sum[0] = ax0 + ax1;
    sum[1] = ay0 + ay1;
    sum[2] = az0 + az1;
    sum[3] = aw0 + aw1;

    // Valid column window for this row
    const int jlo = (i >= 256) ? (i - 256) : 0;
    const int jhi = (i <= 255) ? (i + 256) : (H_DIM - 1);

    #pragma unroll
    for (int k = 0; k < 4; k++) {
        const int j = jbase + k;
        if (j >= jlo && j <= jhi) {
            const int o = j - i + 256;              // diagonal id 0..512
            const int off = o - 256;
            const int dlen = H_DIM - (off < 0 ? -off : off);
            atomicAdd(&out[b * N_OFF + o], sum[k] / ((float)C_DIM * (float)dlen));
        }
    }
}

extern "C" void kernel_launch(void* const* d_in, const int* in_sizes, int n_in,
                              void* d_out, int out_size) {
    const float* x = (const float*)d_in[0];
    float* out = (float*)d_out;

    zero_out_kernel<<<(OUT_ELEMS + 255) / 256, 256>>>(out, OUT_ELEMS);

    diag_pool_kernel<<<NBLOCKS, 256>>>(x, out);
}